// round 10
// baseline (speedup 1.0000x reference)
#include <cuda_runtime.h>
#include <cstdint>

#define NB   256
#define NL   500
#define ND   3
#define NC   32
#define NI   35
#define NH   512
#define NM   5
#define NO   15
#define NOUT 35
#define NP   40       // padded out cols; mod 32 = 8 -> conflict-free B frags
#define NG   36
#define LCH  14
#define BT   32       // batch tile per CTA (2 CTAs/SM)
#define XS_STR 44     // mod 32 = 12 -> conflict-free A frags
#define WS_STR 520    // mod 32 = 8  -> conflict-free B frags
#define SNS    260    // mod 32 = 4  -> conflict-free A frags

// chunk sums -> exclusive chunk prefixes (+b_enc) after k_scan
__device__ float g_S[NG * NB * NH];
// within-chunk inclusive prefixes P[l][b][h]
__device__ float g_C[NL * NB * NH];

// ---------------- helpers ----------------
__device__ __forceinline__ float tf32r(float x) {
    uint32_t u; asm("cvt.rna.tf32.f32 %0, %1;" : "=r"(u) : "f"(x));
    return __uint_as_float(u);
}
__device__ __forceinline__ uint32_t tf32u(float x) {
    uint32_t u; asm("cvt.rna.tf32.f32 %0, %1;" : "=r"(u) : "f"(x));
    return u;
}
__device__ __forceinline__ void mma8(float* c, const uint32_t* a, uint32_t b0, uint32_t b1) {
    asm volatile("mma.sync.aligned.m16n8k8.row.col.f32.tf32.tf32.f32 "
        "{%0,%1,%2,%3}, {%4,%5,%6,%7}, {%8,%9}, {%0,%1,%2,%3};"
        : "+f"(c[0]), "+f"(c[1]), "+f"(c[2]), "+f"(c[3])
        : "r"(a[0]), "r"(a[1]), "r"(a[2]), "r"(a[3]), "r"(b0), "r"(b1));
}
__device__ __forceinline__ void cpa4(uint32_t dst, const void* src) {
    asm volatile("cp.async.ca.shared.global [%0], [%1], 4;" :: "r"(dst), "l"(src) : "memory");
}
__device__ __forceinline__ void cpa16(uint32_t dst, const void* src) {
    asm volatile("cp.async.ca.shared.global [%0], [%1], 16;" :: "r"(dst), "l"(src) : "memory");
}
#define CP_COMMIT() asm volatile("cp.async.commit_group;" ::: "memory")
#define CP_WAIT0()  asm volatile("cp.async.wait_group 0;" ::: "memory")
#define CP_WAIT1()  asm volatile("cp.async.wait_group 1;" ::: "memory")

// -------------------------------------------------------------------------
// K1: per step l: acc += x[l]@W[l] (tf32 mma); store P[l]=acc to g_C; at
// chunk end store acc to g_S. BT=32, 256 threads, 2 CTAs/SM; single-buffered
// W+x staged via cp.async right after the mma sync (peer CTA hides the fetch).
// warps: 2 m-groups (16 rows) x 4 n-groups (128 cols).
// -------------------------------------------------------------------------
__global__ __launch_bounds__(256, 2)
void k_chunksum(const float* __restrict__ inputs, const float* __restrict__ z,
                const float* __restrict__ W_enc)
{
    extern __shared__ float sm[];
    float* xs = sm;                 // 32*44 = 1408 floats
    float* ws = sm + BT * XS_STR;   // 40*520 = 20800 floats

    const int g = blockIdx.x, b0 = blockIdx.y * BT;
    const int l0 = g * LCH, l1 = min(l0 + LCH, NL);
    const int tid = threadIdx.x, lane = tid & 31, warp = tid >> 5;
    const int gid = lane >> 2, tig = lane & 3;
    const int mw = warp & 1, nw = warp >> 1;
    const int mrow0 = mw * 16;

    // zero pads once (rows/cols 35..39; never touched by cp.async)
    for (int i = tid; i < BT * 5; i += 256) xs[(i / 5) * XS_STR + 35 + i % 5] = 0.f;
    for (int i = tid; i < 5 * NH; i += 256) ws[(35 + i / NH) * WS_STR + (i % NH)] = 0.f;

    auto prefetch = [&](int l) {
        uint32_t xb = (uint32_t)__cvta_generic_to_shared(xs);
        uint32_t wb = (uint32_t)__cvta_generic_to_shared(ws);
        for (int idx = tid; idx < BT * NI; idx += 256) {
            int b = idx / NI, k = idx - b * NI;
            const float* src = (k < ND)
                ? inputs + ((size_t)(b0 + b) * NL + l) * ND + k
                : z + ((size_t)(b0 + b) * NL + l) * NC + (k - ND);
            cpa4(xb + (uint32_t)(b * XS_STR + k) * 4u, src);
        }
        const float* wsrc = W_enc + (size_t)l * NI * NH;
        for (int idx = tid; idx < NI * (NH / 4); idx += 256) {
            int k = idx >> 7, h4 = idx & 127;
            cpa16(wb + (uint32_t)(k * WS_STR + h4 * 4) * 4u, wsrc + k * NH + h4 * 4);
        }
    };

    float acc[16][4];
#pragma unroll
    for (int t = 0; t < 16; t++) { acc[t][0] = acc[t][1] = acc[t][2] = acc[t][3] = 0.f; }

    prefetch(l0); CP_COMMIT();

    for (int l = l0; l < l1; l++) {
        CP_WAIT0();
        __syncthreads();

        uint32_t a[5][4];
        {
            const float* p = xs + (mrow0 + gid) * XS_STR + tig;
#pragma unroll
            for (int s = 0; s < 5; s++) {
                a[s][0] = tf32u(p[s * 8]);
                a[s][1] = tf32u(p[8 * XS_STR + s * 8]);
                a[s][2] = tf32u(p[s * 8 + 4]);
                a[s][3] = tf32u(p[8 * XS_STR + s * 8 + 4]);
            }
        }
#pragma unroll
        for (int t = 0; t < 16; t++) {
            const float* wp = ws + nw * 128 + t * 8 + gid;
#pragma unroll
            for (int s = 0; s < 5; s++) {
                uint32_t bb0 = tf32u(wp[(s * 8 + tig) * WS_STR]);
                uint32_t bb1 = tf32u(wp[(s * 8 + tig + 4) * WS_STR]);
                mma8(acc[t], a[s], bb0, bb1);
            }
        }
        __syncthreads();          // all warps done reading xs/ws
        if (l + 1 < l1) prefetch(l + 1);
        CP_COMMIT();

        if (l + 1 < l1) {         // store P[l] (last step of chunk not needed)
            float* d0 = g_C + ((size_t)l * NB + b0 + mrow0 + gid) * NH;
            float* d1 = d0 + 8 * NH;
#pragma unroll
            for (int t = 0; t < 16; t++) {
                int col = nw * 128 + t * 8 + 2 * tig;
                *(float2*)&d0[col] = make_float2(acc[t][0], acc[t][1]);
                *(float2*)&d1[col] = make_float2(acc[t][2], acc[t][3]);
            }
        }
    }

    float* dst = g_S + ((size_t)g * NB + b0 + mrow0 + gid) * NH;
#pragma unroll
    for (int t = 0; t < 16; t++) {
        int col = nw * 128 + t * 8 + 2 * tig;
        *(float2*)&dst[col]          = make_float2(acc[t][0], acc[t][1]);
        *(float2*)&dst[8 * NH + col] = make_float2(acc[t][2], acc[t][3]);
    }
}

// -------------------------------------------------------------------------
// K2: exclusive scan over chunks per (b,h), folding in b_enc.
// -------------------------------------------------------------------------
__global__ void k_scan(const float* __restrict__ b_enc)
{
    const int idx = blockIdx.x * 512 + threadIdx.x;
    const int h = idx & (NH - 1);
    float run = b_enc[h];
#pragma unroll 1
    for (int g = 0; g < NG; g++) {
        size_t off = (size_t)g * NB * NH + idx;
        float v = g_S[off];
        g_S[off] = run;
        run += v;
    }
}

__device__ __forceinline__ float biasv(int l, int o,
        const float* __restrict__ b_mu, const float* __restrict__ b_sigma,
        const float* __restrict__ b_pi) {
    if (o < NO)     return b_mu[(size_t)l * NO + o];
    if (o < 2 * NO) return b_sigma[(size_t)l * NO + (o - NO)];
    return b_pi[(size_t)l * NM + (o - 2 * NO)];
}

// -------------------------------------------------------------------------
// K3: per step: snapshot relu(g_S[g] + P[l-1]) per 256-col k-half (float4),
// stage-B mma (warps = 2m x 4k within half), Vcat double-buffered per half
// via cp.async (snapshot overlaps the wait). BT=32, 256 threads, 2 CTAs/SM.
// -------------------------------------------------------------------------
__global__ __launch_bounds__(256, 2)
void k_main(const float* __restrict__ V_mu, const float* __restrict__ b_mu,
            const float* __restrict__ V_sigma, const float* __restrict__ b_sigma,
            const float* __restrict__ V_pi, const float* __restrict__ b_pi,
            float* __restrict__ out)
{
    extern __shared__ float sm[];
    float* snap = sm;                // 32*260 = 8320 floats (also reduce scratch)
    float* vs   = sm + BT * SNS;     // 2 * 256*40 = 20480 floats

    const int g = blockIdx.x, b0 = blockIdx.y * BT;
    const int l0 = g * LCH, l1 = min(l0 + LCH, NL);
    const int tid = threadIdx.x, lane = tid & 31, warp = tid >> 5;
    const int gid = lane >> 2, tig = lane & 3;
    const int mw = warp & 1, qw = warp >> 1;
    const int mrow0 = mw * 16;
    const int srow = tid >> 3, sc8 = tid & 7;   // snapshot mapping

    // zero pad cols (35..39) of both Vcat slots once
    for (int i = tid; i < 2 * 256 * 5; i += 256) {
        int s = i / (256 * 5), r = i - s * (256 * 5);
        vs[s * 256 * NP + (r / 5) * NP + 35 + r % 5] = 0.f;
    }

    auto prefetch_v = [&](int l, int hs) {
        uint32_t vb = (uint32_t)__cvta_generic_to_shared(vs + hs * 256 * NP);
        for (int idx = tid; idx < 256 * NOUT; idx += 256) {
            int kl = idx / NOUT, o = idx - kl * NOUT;
            int h = hs * 256 + kl;
            const float* src;
            if (o < NO)          src = V_mu    + ((size_t)l * NH + h) * NO + o;
            else if (o < 2 * NO) src = V_sigma + ((size_t)l * NH + h) * NO + (o - NO);
            else                 src = V_pi    + ((size_t)l * NH + h) * NM + (o - 2 * NO);
            cpa4(vb + (uint32_t)(kl * NP + o) * 4u, src);
        }
    };

    const float4* gs4 = (const float4*)(g_S + ((size_t)g * NB + b0) * NH);

    prefetch_v(l0, 0); CP_COMMIT();
    prefetch_v(l0, 1); CP_COMMIT();

    for (int l = l0; l < l1; l++) {
        const float4* pp4 = (l > l0)
            ? (const float4*)(g_C + ((size_t)(l - 1) * NB + b0) * NH) : nullptr;

        float bacc[5][4];
#pragma unroll
        for (int t = 0; t < 5; t++) { bacc[t][0] = bacc[t][1] = bacc[t][2] = bacc[t][3] = 0.f; }

#pragma unroll
        for (int hs = 0; hs < 2; hs++) {
            __syncthreads();   // snap free (prev mma / prev reduce readers done)
            // snapshot: relu(g_S + P[l-1]) for this k-half, float4 path
#pragma unroll
            for (int j = 0; j < 8; j++) {
                int c4 = sc8 + j * 8;                  // 0..63 local float4 col
                float4 v = gs4[srow * (NH / 4) + hs * 64 + c4];
                if (pp4) {
                    float4 p = pp4[srow * (NH / 4) + hs * 64 + c4];
                    v.x += p.x; v.y += p.y; v.z += p.z; v.w += p.w;
                }
                float4 t;
                t.x = tf32r(fmaxf(v.x, 0.f));
                t.y = tf32r(fmaxf(v.y, 0.f));
                t.z = tf32r(fmaxf(v.z, 0.f));
                t.w = tf32r(fmaxf(v.w, 0.f));
                *(float4*)(snap + srow * SNS + 4 * c4) = t;
            }
            CP_WAIT1();        // Vcat for this half arrived (next half may be in flight)
            __syncthreads();

            const float* ap = snap + (mrow0 + gid) * SNS + qw * 64 + tig;
            const float* vbase = vs + hs * 256 * NP;
#pragma unroll
            for (int s = 0; s < 8; s++) {
                uint32_t a[4];
                a[0] = __float_as_uint(ap[s * 8]);
                a[1] = __float_as_uint(ap[8 * SNS + s * 8]);
                a[2] = __float_as_uint(ap[s * 8 + 4]);
                a[3] = __float_as_uint(ap[8 * SNS + s * 8 + 4]);
                const float* vp = vbase + (qw * 64 + s * 8 + tig) * NP + gid;
#pragma unroll
                for (int t = 0; t < 5; t++) {
                    uint32_t bb0 = tf32u(vp[t * 8]);
                    uint32_t bb1 = tf32u(vp[4 * NP + t * 8]);
                    mma8(bacc[t], a, bb0, bb1);
                }
            }
            __syncthreads();   // slot consumed -> safe to refill
            if (l + 1 < l1) prefetch_v(l + 1, hs);
            CP_COMMIT();       // empty commit at tail keeps wait_group counting valid
        }

        // 4-way k-reduction through snap scratch (free: both halves consumed)
        if (qw != 0) {
            float* red = snap + (qw - 1) * (BT * NP);
#pragma unroll
            for (int t = 0; t < 5; t++) {
                int col = t * 8 + 2 * tig, row = mrow0 + gid;
                *(float2*)&red[row * NP + col]       = make_float2(bacc[t][0], bacc[t][1]);
                *(float2*)&red[(row + 8) * NP + col] = make_float2(bacc[t][2], bacc[t][3]);
            }
        }
        __syncthreads();
        if (qw == 0) {
#pragma unroll
            for (int t = 0; t < 5; t++) {
                int col = t * 8 + 2 * tig, row = mrow0 + gid;
                float v0 = bacc[t][0], v1 = bacc[t][1];
                float v2 = bacc[t][2], v3 = bacc[t][3];
#pragma unroll
                for (int kg = 0; kg < 3; kg++) {
                    const float* r0 = snap + kg * (BT * NP) + row * NP + col;
                    v0 += r0[0]; v1 += r0[1];
                    v2 += r0[8 * NP]; v3 += r0[8 * NP + 1];
                }
                size_t ob  = ((size_t)(b0 + row) * NL + l) * NOUT + col;
                size_t ob2 = ((size_t)(b0 + row + 8) * NL + l) * NOUT + col;
                if (col < NOUT) {
                    float bb = biasv(l, col, b_mu, b_sigma, b_pi);
                    out[ob] = v0 + bb; out[ob2] = v2 + bb;
                }
                if (col + 1 < NOUT) {
                    float bb = biasv(l, col + 1, b_mu, b_sigma, b_pi);
                    out[ob + 1] = v1 + bb; out[ob2 + 1] = v3 + bb;
                }
            }
        }
        // loop-top __syncthreads protects snap before next snapshot
    }
}

// -------------------------------------------------------------------------
extern "C" void kernel_launch(void* const* d_in, const int* in_sizes, int n_in,
                              void* d_out, int out_size)
{
    const float* inputs  = (const float*)d_in[0];
    const float* z       = (const float*)d_in[1];
    const float* W_enc   = (const float*)d_in[2];
    const float* b_enc   = (const float*)d_in[3];
    const float* V_mu    = (const float*)d_in[4];
    const float* b_mu    = (const float*)d_in[5];
    const float* V_sigma = (const float*)d_in[6];
    const float* b_sigma = (const float*)d_in[7];
    const float* V_pi    = (const float*)d_in[8];
    const float* b_pi    = (const float*)d_in[9];
    float* out = (float*)d_out;

    const int SMEM_K1 = (BT * XS_STR + 40 * WS_STR) * 4;   //  88,832 B
    const int SMEM_K3 = (BT * SNS + 2 * 256 * NP) * 4;     // 115,200 B

    cudaFuncSetAttribute(k_chunksum, cudaFuncAttributeMaxDynamicSharedMemorySize, SMEM_K1);
    cudaFuncSetAttribute(k_main,     cudaFuncAttributeMaxDynamicSharedMemorySize, SMEM_K3);

    k_chunksum<<<dim3(NG, NB / BT), 256, SMEM_K1>>>(inputs, z, W_enc);
    k_scan<<<(NB * NH) / 512, 512>>>(b_enc);
    k_main<<<dim3(NG, NB / BT), 256, SMEM_K3>>>(
        V_mu, b_mu, V_sigma, b_sigma, V_pi, b_pi, out);
}